// round 3
// baseline (speedup 1.0000x reference)
#include <cuda_runtime.h>
#include <cstdint>
#include <math.h>

#define T_SEQ 512
#define NB    256
#define KIN   300
#define HID   256

typedef unsigned long long ull;

// ---------------- static scratch (no allocations allowed) ----------------
__device__ float g_xp[(size_t)T_SEQ * NB * HID];   // xp[t][b][h], 128 MB
__device__ float g_hT[NB * HID];                   // final hidden state

// ---------------- packed dual-FP32 helpers (sm_10x f32x2 path) -----------
__device__ __forceinline__ ull fma2(ull a, ull b, ull c) {
    ull d;
    asm("fma.rn.f32x2 %0, %1, %2, %3;" : "=l"(d) : "l"(a), "l"(b), "l"(c));
    return d;
}
__device__ __forceinline__ float2 unpk(ull v) {
    float2 u;
    asm("mov.b64 {%0, %1}, %2;" : "=f"(u.x), "=f"(u.y) : "l"(v));
    return u;
}

// =========================================================================
// GEMM: g_xp[m][n] = sum_k x[m][k] * W_ih[n][k] + b_ih[n] + b_hh[n]
//   M = T_SEQ*NB = 131072, N = HID = 256, K = KIN = 300
//   Tile 128(m) x 64(n), K-chunk 12, 256 threads.
//   Thread grid: tn = tid&15 (fast, n -> coalesced stores), tm = tid>>4.
//   Each thread: 4 m-pairs x 4 n cols, f32x2 accumulators over the m-pair.
//   B tile stored duplicated so (b,b) pair = one LDS.64.
// =========================================================================
#define MT 128
#define NT 64
#define KC 12
#define NCHUNK 25   // 25*12 = 300 exactly

__global__ __launch_bounds__(256) void gemm_kernel(
    const float* __restrict__ A, const float* __restrict__ W,
    const float* __restrict__ b_ih, const float* __restrict__ b_hh)
{
    __shared__ __align__(16) float a_sh[2][KC * MT];
    __shared__ __align__(16) float b_sh[2][KC * NT * 2];

    const int tid = threadIdx.x;
    const int tn = tid & 15;
    const int tm = tid >> 4;
    const int m0 = blockIdx.x * MT;
    const int n0 = blockIdx.y * NT;

    // Per-thread global->smem assignments (constant across chunks).
    int aoff[6], asls[6];
#pragma unroll
    for (int j = 0; j < 6; ++j) {
        int idx = tid + 256 * j;           // 1536 = 128m x 12k
        int m = idx / KC, ki = idx - m * KC;
        aoff[j] = m * KIN + ki;
        asls[j] = ki * MT + m;
    }
    int boff[3], bsls[3];
#pragma unroll
    for (int j = 0; j < 3; ++j) {
        int idx = tid + 256 * j;           // 768 = 64n x 12k
        int n = idx / KC, ki = idx - n * KC;
        boff[j] = n * KIN + ki;
        bsls[j] = ki * (NT * 2) + 2 * n;
    }
    const float* Ab = A + (size_t)m0 * KIN;
    const float* Wb = W + (size_t)n0 * KIN;

    ull acc[4][4];
#pragma unroll
    for (int i = 0; i < 4; ++i)
#pragma unroll
        for (int j = 0; j < 4; ++j) acc[i][j] = 0ull;

    // Prologue: load chunk 0 into buffer 0.
    float aR[6], bR[3];
#pragma unroll
    for (int j = 0; j < 6; ++j) aR[j] = __ldg(Ab + aoff[j]);
#pragma unroll
    for (int j = 0; j < 3; ++j) bR[j] = __ldg(Wb + boff[j]);
#pragma unroll
    for (int j = 0; j < 6; ++j) a_sh[0][asls[j]] = aR[j];
#pragma unroll
    for (int j = 0; j < 3; ++j) { b_sh[0][bsls[j]] = bR[j]; b_sh[0][bsls[j] + 1] = bR[j]; }

    for (int c = 0; c < NCHUNK; ++c) {
        __syncthreads();                   // buf[c&1] ready; old readers done
        const int buf = c & 1;
        if (c + 1 < NCHUNK) {
            const int k0 = (c + 1) * KC;
#pragma unroll
            for (int j = 0; j < 6; ++j) aR[j] = __ldg(Ab + aoff[j] + k0);
#pragma unroll
            for (int j = 0; j < 3; ++j) bR[j] = __ldg(Wb + boff[j] + k0);
        }
#pragma unroll
        for (int ki = 0; ki < KC; ++ki) {
            const ull* ap = (const ull*)(a_sh[buf] + ki * MT);
            const ull* bp = (const ull*)(b_sh[buf] + ki * NT * 2);
            ull av[4], bv[4];
#pragma unroll
            for (int mp = 0; mp < 4; ++mp) av[mp] = ap[tm * 4 + mp];
#pragma unroll
            for (int nj = 0; nj < 4; ++nj) bv[nj] = bp[tn + 16 * nj];
#pragma unroll
            for (int mp = 0; mp < 4; ++mp)
#pragma unroll
                for (int nj = 0; nj < 4; ++nj)
                    acc[mp][nj] = fma2(av[mp], bv[nj], acc[mp][nj]);
        }
        if (c + 1 < NCHUNK) {
            const int nb = 1 - buf;
#pragma unroll
            for (int j = 0; j < 6; ++j) a_sh[nb][asls[j]] = aR[j];
#pragma unroll
            for (int j = 0; j < 3; ++j) { b_sh[nb][bsls[j]] = bR[j]; b_sh[nb][bsls[j] + 1] = bR[j]; }
        }
    }

    // Epilogue: add bias, store (lanes = tn fast -> coalesced 64B runs).
    float bias[4];
#pragma unroll
    for (int nj = 0; nj < 4; ++nj) {
        int cc = n0 + tn + 16 * nj;
        bias[nj] = __ldg(b_ih + cc) + __ldg(b_hh + cc);
    }
#pragma unroll
    for (int mp = 0; mp < 4; ++mp) {
        int r = m0 + tm * 8 + 2 * mp;
#pragma unroll
        for (int nj = 0; nj < 4; ++nj) {
            int cc = n0 + tn + 16 * nj;
            float2 u = unpk(acc[mp][nj]);
            g_xp[(size_t)r * HID + cc]       = u.x + bias[nj];
            g_xp[(size_t)(r + 1) * HID + cc] = u.y + bias[nj];
        }
    }
}

// =========================================================================
// Recurrent scan: 128 CTAs, each owns batches (2c, 2c+1), all 256 h-rows.
//   Thread tid = output row h. W_hh[tid][0:128) in 64 packed-f32x2 regs,
//   W_hh[tid][128:256) in 128 KB smem (k-major, conflict-free).
//   h double-buffered, interleaved (h0[k],h0[k+1],h1[k],h1[k+1]) so one
//   broadcast LDS.128 feeds both batches' k-pair fma2.
// =========================================================================
#define SCAN_SMEM (64 * 256 * (int)sizeof(float2) + 2 * 128 * (int)sizeof(float4))

__global__ __launch_bounds__(256, 1) void scan_kernel(const float* __restrict__ W_hh)
{
    extern __shared__ char smraw[];
    float2* w_sh = (float2*)smraw;                       // [64 kpairs][256 h]
    float4* h_sh = (float4*)(smraw + 64 * 256 * 8);      // [2 buf][128 kpairs]

    const int tid = threadIdx.x;
    const int b0 = blockIdx.x * 2, b1 = b0 + 1;

    // Register half of this thread's W_hh row (k in [0,128) as 64 pairs).
    ull wreg[64];
    const ull* wrow = (const ull*)(W_hh + tid * HID);
#pragma unroll
    for (int j = 0; j < 64; ++j) wreg[j] = __ldg(wrow + j);

    // Smem half (k in [128,256)), k-major so compute loads are conflict-free.
    const float2* wrow2 = (const float2*)(W_hh + tid * HID + 128);
    for (int j = 0; j < 64; ++j) w_sh[j * 256 + tid] = __ldg(wrow2 + j);

    if (tid < 128) h_sh[tid] = make_float4(0.f, 0.f, 0.f, 0.f);  // h = 0
    __syncthreads();

    const float* xp0 = g_xp + (size_t)b0 * HID + tid;
    const float* xp1 = g_xp + (size_t)b1 * HID + tid;

    float v0 = 0.f, v1 = 0.f;
    for (int t = 0; t < T_SEQ; ++t) {
        // Issue xp loads early; consumed only after the ~1000-cycle MAC loop.
        const float xv0 = __ldg(xp0 + (size_t)t * NB * HID);
        const float xv1 = __ldg(xp1 + (size_t)t * NB * HID);

        const ulonglong2* hb = (const ulonglong2*)(h_sh + (t & 1) * 128);
        ull acc0 = 0ull, acc1 = 0ull;
#pragma unroll
        for (int kp = 0; kp < 64; ++kp) {               // register-weight half
            ulonglong2 hv = hb[kp];                     // broadcast LDS.128
            acc0 = fma2(wreg[kp], hv.x, acc0);
            acc1 = fma2(wreg[kp], hv.y, acc1);
        }
#pragma unroll 16
        for (int kp = 0; kp < 64; ++kp) {               // smem-weight half
            ulonglong2 hv = hb[64 + kp];
            ull wv = *(const ull*)(w_sh + kp * 256 + tid);
            acc0 = fma2(wv, hv.x, acc0);
            acc1 = fma2(wv, hv.y, acc1);
        }
        float2 u0 = unpk(acc0), u1 = unpk(acc1);
        v0 = tanhf(u0.x + u0.y + xv0);
        v1 = tanhf(u1.x + u1.y + xv1);

        float* wb = (float*)(h_sh + ((t + 1) & 1) * 128);
        wb[(tid >> 1) * 4 + (tid & 1)]     = v0;
        wb[(tid >> 1) * 4 + 2 + (tid & 1)] = v1;
        __syncthreads();
    }
    g_hT[b0 * HID + tid] = v0;
    g_hT[b1 * HID + tid] = v1;
}

// =========================================================================
// Head: logits = hT @ W_fc^T + b_fc; out = log_softmax(logits)
// =========================================================================
__global__ void head_kernel(const float* __restrict__ W_fc,
                            const float* __restrict__ b_fc,
                            float* __restrict__ out)
{
    const int b = blockIdx.x, tid = threadIdx.x;   // 32 threads per block
    float s0 = 0.f, s1 = 0.f;
    for (int h = tid; h < HID; h += 32) {
        float hv = g_hT[b * HID + h];
        s0 += hv * __ldg(W_fc + h);
        s1 += hv * __ldg(W_fc + HID + h);
    }
#pragma unroll
    for (int off = 16; off; off >>= 1) {
        s0 += __shfl_xor_sync(0xffffffffu, s0, off);
        s1 += __shfl_xor_sync(0xffffffffu, s1, off);
    }
    if (tid == 0) {
        float l0 = s0 + __ldg(b_fc), l1 = s1 + __ldg(b_fc + 1);
        float m = fmaxf(l0, l1);
        float lse = m + logf(expf(l0 - m) + expf(l1 - m));
        out[2 * b]     = l0 - lse;
        out[2 * b + 1] = l1 - lse;
    }
}

// =========================================================================
extern "C" void kernel_launch(void* const* d_in, const int* in_sizes, int n_in,
                              void* d_out, int out_size)
{
    const float* x    = (const float*)d_in[0];
    const float* W_ih = (const float*)d_in[1];
    const float* W_hh = (const float*)d_in[2];
    const float* b_ih = (const float*)d_in[3];
    const float* b_hh = (const float*)d_in[4];
    const float* W_fc = (const float*)d_in[5];
    const float* b_fc = (const float*)d_in[6];
    float* out = (float*)d_out;

    cudaFuncSetAttribute(scan_kernel,
                         cudaFuncAttributeMaxDynamicSharedMemorySize, SCAN_SMEM);

    gemm_kernel<<<dim3(1024, 4, 1), 256>>>(x, W_ih, b_ih, b_hh);
    scan_kernel<<<128, 256, SCAN_SMEM>>>(W_hh);
    head_kernel<<<256, 32>>>(W_fc, b_fc, out);
}